// round 1
// baseline (speedup 1.0000x reference)
#include <cuda_runtime.h>
#include <math.h>

#define BB 8
#define NN 2048
#define CC 32
#define DD 64
#define QQ 256
#define KK 205
#define JP 36           // padded j dimension (33 -> 36 for float4)
#define RANK (KK-1)

// ---------------- scratch (__device__ globals; no allocations allowed) ----
__device__ float d_xl[BB*NN*CC];        // 2 MB
__device__ int   d_ind[QQ*KK];
__device__ float d_g[QQ*KK*JP];         // 7.6 MB

__device__ __forceinline__ float gelu_f(float x){
    return 0.5f*x*(1.0f+erff(x*0.70710678118654752440f));
}

// ---------------- kernel A: xl = x @ W_lin + b_lin ------------------------
__global__ __launch_bounds__(256) void k_xl(const float* __restrict__ x,
                                            const float* __restrict__ W,
                                            const float* __restrict__ bl){
    __shared__ float sW[CC*CC];
    int tid = threadIdx.x;
    for(int i=tid;i<CC*CC;i+=256) sW[i]=W[i];
    __syncthreads();
    int row  = blockIdx.x*8 + (tid>>5);
    int lane = tid&31;
    float xv  = x[row*CC + lane];
    float acc = bl[lane];
    #pragma unroll
    for(int ci=0;ci<CC;ci++)
        acc = fmaf(__shfl_sync(0xffffffffu, xv, ci), sW[ci*CC+lane], acc);
    d_xl[row*CC+lane] = acc;
}

// ---------------- copy query_pos into output tail -------------------------
__global__ void k_qp(const float* __restrict__ qp, float* __restrict__ out){
    int i = threadIdx.x;
    if(i < QQ*2) out[BB*QQ*DD + i] = qp[i];
}

// ---------------- kernel B: per-query knn select + weights + g ------------
__global__ __launch_bounds__(256) void k_select(
        const float* __restrict__ pos, const float* __restrict__ qpos,
        const float* __restrict__ rffB,
        const float* __restrict__ W1,  const float* __restrict__ b1,
        const float* __restrict__ qmw, const float* __restrict__ qmo)
{
    __shared__ float sed[NN];              // edist for all n
    __shared__ unsigned int hist[256];
    __shared__ int   sidx[KK];
    __shared__ float sd0[KK], sd1[KK], sedk[KK], skd[KK];
    __shared__ float sfeat[KK][32];
    __shared__ float sW1[CC*CC];
    __shared__ float sb1[CC];
    __shared__ unsigned int s_prefix, s_r, s_cnt;
    __shared__ float rbufA[8], rbufB[8];
    __shared__ float s_min, s_max, s_sum;

    const int q = blockIdx.x, tid = threadIdx.x;
    const int warp = tid>>5, lane = tid&31;
    const float qx = qpos[q*2], qy = qpos[q*2+1];

    for(int i=tid;i<CC*CC;i+=256) sW1[i]=W1[i];
    if(tid<CC) sb1[tid]=b1[tid];

    // edist (wrapped torus distance)
    for(int n=tid;n<NN;n+=256){
        float d0 = qx - pos[n*2];   d0 += 0.5f; d0 -= floorf(d0); d0 -= 0.5f;
        float d1 = qy - pos[n*2+1]; d1 += 0.5f; d1 -= floorf(d1); d1 -= 0.5f;
        sed[n] = d0*d0 + d1*d1;
    }
    if(tid==0){ s_prefix=0u; s_r=RANK; s_cnt=0u; }
    __syncthreads();

    // MSD radix select: value of rank-204 (0-indexed) smallest; keys = float bits (all >= 0)
    for(int pass=0; pass<4; ++pass){
        const int shift = 24 - 8*pass;
        for(int i=tid;i<256;i+=256) hist[i]=0u;
        __syncthreads();
        const unsigned int prefix = s_prefix;
        const unsigned int hm = (pass==0) ? 0u : (0xFFFFFFFFu << (shift+8));
        for(int n=tid;n<NN;n+=256){
            unsigned int k = __float_as_uint(sed[n]);
            if((k & hm) == prefix) atomicAdd(&hist[(k>>shift)&255u], 1u);
        }
        __syncthreads();
        if(tid==0){
            unsigned int cum=0, rr=s_r; int bsel=255;
            for(int bkt=0;bkt<256;bkt++){
                unsigned int c=hist[bkt];
                if(cum + c > rr){ bsel=bkt; break; }
                cum += c;
            }
            s_prefix = prefix | ((unsigned int)bsel << shift);
            s_r = rr - cum;
        }
        __syncthreads();
    }
    const unsigned int T = s_prefix;

    // compact the K nearest: first strictly-less, then equals (capped)
    for(int n=tid;n<NN;n+=256){
        unsigned int k = __float_as_uint(sed[n]);
        if(k < T){ unsigned int p = atomicAdd(&s_cnt,1u); sidx[p]=n; }
    }
    __syncthreads();
    for(int n=tid;n<NN;n+=256){
        unsigned int k = __float_as_uint(sed[n]);
        if(k == T){ unsigned int p = atomicAdd(&s_cnt,1u); if(p<KK) sidx[p]=n; }
    }
    __syncthreads();

    // gather dist + edist for the selected set
    for(int k2=tid;k2<KK;k2+=256){
        int n = sidx[k2];
        float d0 = qx - pos[n*2];   d0 += 0.5f; d0 -= floorf(d0); d0 -= 0.5f;
        float d1 = qy - pos[n*2+1]; d1 += 0.5f; d1 -= floorf(d1); d1 -= 0.5f;
        sd0[k2]=d0; sd1[k2]=d1; sedk[k2]=sed[n];
    }
    __syncthreads();

    // min/max over selected
    float mn = 1e30f, mx = -1e30f;
    for(int k2=tid;k2<KK;k2+=256){ mn=fminf(mn,sedk[k2]); mx=fmaxf(mx,sedk[k2]); }
    #pragma unroll
    for(int o=16;o>0;o>>=1){
        mn = fminf(mn, __shfl_down_sync(0xffffffffu,mn,o));
        mx = fmaxf(mx, __shfl_down_sync(0xffffffffu,mx,o));
    }
    if(lane==0){ rbufA[warp]=mn; rbufB[warp]=mx; }
    __syncthreads();
    if(tid==0){
        float a=rbufA[0], b=rbufB[0];
        for(int w=1;w<8;w++){ a=fminf(a,rbufA[w]); b=fmaxf(b,rbufB[w]); }
        s_min=a; s_max=b;
    }
    __syncthreads();

    // softmax weights over K (logit max is exactly 0 at the min-dist element)
    const float inv = 1.0f/(s_max - s_min + 1e-8f);
    float lsum = 0.0f;
    for(int k2=tid;k2<KK;k2+=256){
        float w = expf(-(sedk[k2]-s_min)*inv);
        skd[k2]=w; lsum+=w;
    }
    #pragma unroll
    for(int o=16;o>0;o>>=1) lsum += __shfl_down_sync(0xffffffffu,lsum,o);
    if(lane==0) rbufA[warp]=lsum;
    __syncthreads();
    if(tid==0){
        float s=0.f; for(int w=0;w<8;w++) s+=rbufA[w];
        s_sum=s;
    }
    __syncthreads();
    const float invsum = 1.0f/s_sum;

    // RFF features: feat = [sin(2pi dist@B), cos(2pi dist@B)]
    for(int i=tid;i<KK*16;i+=256){
        int k2=i>>4, j=i&15;
        float pr = 6.28318530717958647692f*(sd0[k2]*rffB[j] + sd1[k2]*rffB[16+j]);
        float s,c; sincosf(pr,&s,&c);
        sfeat[k2][j]=s; sfeat[k2][16+j]=c;
    }
    __syncthreads();

    // h = (feat@W1+b1)*qmw+qmo ; g = gelu(h)*kd, plus kd channel, zero pad
    for(int i=tid;i<KK*CC;i+=256){
        int k2=i>>5, ii=i&31;
        float acc = sb1[ii];
        #pragma unroll
        for(int f=0;f<CC;f++) acc = fmaf(sfeat[k2][f], sW1[f*CC+ii], acc);
        float h  = acc*qmw[q*CC+ii] + qmo[q*CC+ii];
        d_g[(q*KK + k2)*JP + ii] = gelu_f(h) * (skd[k2]*invsum);
    }
    for(int k2=tid;k2<KK;k2+=256){
        float* gr = &d_g[(q*KK + k2)*JP];
        gr[32] = skd[k2]*invsum;
        gr[33] = 0.f; gr[34] = 0.f; gr[35] = 0.f;
        d_ind[q*KK + k2] = sidx[k2];
    }
}

// ---------------- kernel C: gather + M-GEMM + W2 contraction + MLP --------
// dynamic smem layout (floats):
#define OFF_G   0                 // 205*36  = 7380
#define OFF_X   7380              // 103*256 = 26368  (reused as sM 33*256)
#define OFF_IND 33748             // 205 ints (padded to 208)
#define OFF_Y   33956             // 512
#define OFF_H1  34468             // 2048
#define SMEM_FLOATS 36516
#define SMEM_BYTES (SMEM_FLOATS*4)

__global__ __launch_bounds__(288,1) void k_main(
        const float* __restrict__ W2,  const float* __restrict__ filt,
        const float* __restrict__ bias,
        const float* __restrict__ Wm1, const float* __restrict__ bm1,
        const float* __restrict__ Wm2, const float* __restrict__ bm2,
        float* __restrict__ out)
{
    extern __shared__ float smem[];
    float* sg  = smem + OFF_G;
    float* sx  = smem + OFF_X;
    int*   sind= (int*)(smem + OFF_IND);
    float* sy  = smem + OFF_Y;
    float* sh1 = smem + OFF_H1;

    const int q = blockIdx.x, tid = threadIdx.x;
    const int jg = tid>>5;     // 0..8  (j-group of 4)
    const int cg = tid&31;     // 0..31 (col-group of 8, col = b*32+c)

    for(int i=tid;i<KK;i+=288) sind[i]=d_ind[q*KK+i];
    {   const float4* gsrc = (const float4*)&d_g[q*KK*JP];
        float4* gdst = (float4*)sg;
        for(int i=tid;i<KK*(JP/4);i+=288) gdst[i]=gsrc[i];
    }
    __syncthreads();

    float acc[4][8];
    #pragma unroll
    for(int jj=0;jj<4;jj++)
        #pragma unroll
        for(int cc=0;cc<8;cc++) acc[jj][cc]=0.f;

    const float4* sg4 = (const float4*)sg;

    #pragma unroll
    for(int half=0; half<2; ++half){
        const int k0 = half ? 103 : 0;
        const int k1 = half ? KK  : 103;
        const int nk = k1 - k0;
        // gather xl rows for all 8 batches: sx[kk][b*32+c]
        for(int i=tid; i<nk*64; i+=288){
            int kk = i>>6, ch = i&63;           // ch = b*8 + c4
            int b  = ch>>3, c4 = ch&7;
            int n  = sind[k0+kk];
            const float4* src = (const float4*)&d_xl[((b<<11)+n)*CC];
            ((float4*)&sx[kk*256])[ch] = src[c4];
        }
        __syncthreads();
        const float4* sx4 = (const float4*)sx;
        #pragma unroll 2
        for(int kk=0; kk<nk; ++kk){
            float4 g4 = sg4[(k0+kk)*(JP/4) + jg];
            float4 xa = sx4[kk*64 + (cg<<1)];
            float4 xb = sx4[kk*64 + (cg<<1) + 1];
            float xs[8] = {xa.x,xa.y,xa.z,xa.w,xb.x,xb.y,xb.z,xb.w};
            float gs[4] = {g4.x,g4.y,g4.z,g4.w};
            #pragma unroll
            for(int jj=0;jj<4;jj++)
                #pragma unroll
                for(int cc=0;cc<8;cc++)
                    acc[jj][cc] = fmaf(gs[jj], xs[cc], acc[jj][cc]);
        }
        __syncthreads();
    }

    // stage M (33 x 256) into smem (aliases sx; all reads done)
    float* sM = sx;
    #pragma unroll
    for(int jj=0;jj<4;jj++){
        int j = jg*4 + jj;
        if(j < 33){
            #pragma unroll
            for(int cc=0;cc<8;cc++) sM[j*256 + cg*8 + cc] = acc[jj][cc];
        }
    }
    __syncthreads();

    // y[b,d] = sum_{j,c} M[j,b*32+c]*W2ext[j,c,d]; 2 batches per thread share W2 loads
    for(int o=tid; o<256; o+=288){
        int b = o>>6, d = o&63;                 // b in 0..3, pair with b+4
        float a0=0.f, a1=0.f;
        for(int j=0;j<33;j++){
            const float* wrow = (j<32) ? (W2 + j*2048 + d) : (filt + d);
            const float* m0 = &sM[j*256 + b*32];
            const float* m1 = m0 + 128;
            #pragma unroll
            for(int c=0;c<32;c++){
                float w = wrow[c*64];
                a0 = fmaf(m0[c], w, a0);
                a1 = fmaf(m1[c], w, a1);
            }
        }
        sy[b*64+d]     = gelu_f(a0 + bias[d]);
        sy[(b+4)*64+d] = gelu_f(a1 + bias[d]);
    }
    __syncthreads();

    // h1 = gelu(y @ Wm1 + bm1)
    for(int oi=tid; oi<BB*256; oi+=288){
        int b = oi>>8, i = oi&255;
        float a = bm1[i];
        const float* yr = &sy[b*64];
        #pragma unroll
        for(int d2=0; d2<64; ++d2) a = fmaf(yr[d2], Wm1[d2*256+i], a);
        sh1[oi] = gelu_f(a);
    }
    __syncthreads();

    // out = h1 @ Wm2 + bm2 + y
    for(int o=tid; o<BB*DD; o+=288){
        int b = o>>6, d = o&63;
        float a = bm2[d];
        const float* hr = &sh1[b*256];
        #pragma unroll
        for(int i=0;i<256;++i) a = fmaf(hr[i], Wm2[i*64+d], a);
        out[(b*QQ + q)*DD + d] = a + sy[o];
    }
}

// ---------------- launch --------------------------------------------------
extern "C" void kernel_launch(void* const* d_in, const int* in_sizes, int n_in,
                              void* d_out, int out_size){
    (void)in_sizes; (void)n_in; (void)out_size;
    const float* x     = (const float*)d_in[0];
    const float* pos   = (const float*)d_in[1];
    const float* qpos  = (const float*)d_in[2];
    const float* qmw   = (const float*)d_in[3];
    const float* qmo   = (const float*)d_in[4];
    const float* W_lin = (const float*)d_in[5];
    const float* b_lin = (const float*)d_in[6];
    const float* rffB  = (const float*)d_in[7];
    const float* W1    = (const float*)d_in[8];
    const float* b1    = (const float*)d_in[9];
    const float* W2    = (const float*)d_in[10];
    const float* filt  = (const float*)d_in[11];
    const float* bias  = (const float*)d_in[12];
    const float* Wm1   = (const float*)d_in[13];
    const float* bm1   = (const float*)d_in[14];
    const float* Wm2   = (const float*)d_in[15];
    const float* bm2   = (const float*)d_in[16];
    float* out = (float*)d_out;

    cudaFuncSetAttribute(k_main, cudaFuncAttributeMaxDynamicSharedMemorySize, SMEM_BYTES);

    k_xl    <<<BB*NN/8, 256>>>(x, W_lin, b_lin);
    k_qp    <<<1, 512>>>(qpos, out);
    k_select<<<QQ, 256>>>(pos, qpos, rffB, W1, b1, qmw, qmo);
    k_main  <<<QQ, 288, SMEM_BYTES>>>(W2, filt, bias, Wm1, bm1, Wm2, bm2, out);
}

// round 2
// speedup vs baseline: 1.1826x; 1.1826x over previous
#include <cuda_runtime.h>
#include <math.h>

#define BB 8
#define NN 2048
#define CC 32
#define DD 64
#define QQ 256
#define KK 205
#define JP 36           // padded j dimension (33 -> 36 for float4)
#define RANK (KK-1)

// ---------------- scratch (__device__ globals; no allocations allowed) ----
__device__ float d_xl[BB*NN*CC];        // 2 MB
__device__ int   d_ind[QQ*KK];
__device__ float d_g[QQ*KK*JP];         // 7.6 MB

__device__ __forceinline__ float gelu_f(float x){
    return 0.5f*x*(1.0f+erff(x*0.70710678118654752440f));
}

// ---------------- kernel A: xl = x @ W_lin + b_lin ------------------------
__global__ __launch_bounds__(256) void k_xl(const float* __restrict__ x,
                                            const float* __restrict__ W,
                                            const float* __restrict__ bl){
    __shared__ float sW[CC*CC];
    int tid = threadIdx.x;
    for(int i=tid;i<CC*CC;i+=256) sW[i]=W[i];
    __syncthreads();
    int row  = blockIdx.x*8 + (tid>>5);
    int lane = tid&31;
    float xv  = x[row*CC + lane];
    float acc = bl[lane];
    #pragma unroll
    for(int ci=0;ci<CC;ci++)
        acc = fmaf(__shfl_sync(0xffffffffu, xv, ci), sW[ci*CC+lane], acc);
    d_xl[row*CC+lane] = acc;
}

// ---------------- copy query_pos into output tail -------------------------
__global__ void k_qp(const float* __restrict__ qp, float* __restrict__ out){
    int i = threadIdx.x;
    if(i < QQ*2) out[BB*QQ*DD + i] = qp[i];
}

// ---------------- kernel B: per-query knn select + weights + g ------------
__global__ __launch_bounds__(256) void k_select(
        const float* __restrict__ pos, const float* __restrict__ qpos,
        const float* __restrict__ rffB,
        const float* __restrict__ W1,  const float* __restrict__ b1,
        const float* __restrict__ qmw, const float* __restrict__ qmo)
{
    __shared__ float sed[NN];              // edist for all n
    __shared__ unsigned int hist[256];
    __shared__ int   sidx[KK];
    __shared__ float sd0[KK], sd1[KK], sedk[KK], skd[KK];
    __shared__ float sfeat[KK][32];
    __shared__ float sW1[CC*CC];
    __shared__ float sb1[CC];
    __shared__ unsigned int s_prefix, s_r, s_cnt;
    __shared__ float rbufA[8], rbufB[8];
    __shared__ float s_min, s_max, s_sum;

    const int q = blockIdx.x, tid = threadIdx.x;
    const int warp = tid>>5, lane = tid&31;
    const float qx = qpos[q*2], qy = qpos[q*2+1];

    for(int i=tid;i<CC*CC;i+=256) sW1[i]=W1[i];
    if(tid<CC) sb1[tid]=b1[tid];

    // edist (wrapped torus distance)
    for(int n=tid;n<NN;n+=256){
        float d0 = qx - pos[n*2];   d0 += 0.5f; d0 -= floorf(d0); d0 -= 0.5f;
        float d1 = qy - pos[n*2+1]; d1 += 0.5f; d1 -= floorf(d1); d1 -= 0.5f;
        sed[n] = d0*d0 + d1*d1;
    }
    if(tid==0){ s_prefix=0u; s_r=RANK; s_cnt=0u; }
    __syncthreads();

    // MSD radix select: value of rank-204 (0-indexed) smallest; keys = float bits (all >= 0)
    for(int pass=0; pass<4; ++pass){
        const int shift = 24 - 8*pass;
        for(int i=tid;i<256;i+=256) hist[i]=0u;
        __syncthreads();
        const unsigned int prefix = s_prefix;
        const unsigned int hm = (pass==0) ? 0u : (0xFFFFFFFFu << (shift+8));
        for(int n=tid;n<NN;n+=256){
            unsigned int k = __float_as_uint(sed[n]);
            if((k & hm) == prefix) atomicAdd(&hist[(k>>shift)&255u], 1u);
        }
        __syncthreads();
        if(tid==0){
            unsigned int cum=0, rr=s_r; int bsel=255;
            for(int bkt=0;bkt<256;bkt++){
                unsigned int c=hist[bkt];
                if(cum + c > rr){ bsel=bkt; break; }
                cum += c;
            }
            s_prefix = prefix | ((unsigned int)bsel << shift);
            s_r = rr - cum;
        }
        __syncthreads();
    }
    const unsigned int T = s_prefix;

    // compact the K nearest: first strictly-less, then equals (capped)
    for(int n=tid;n<NN;n+=256){
        unsigned int k = __float_as_uint(sed[n]);
        if(k < T){ unsigned int p = atomicAdd(&s_cnt,1u); sidx[p]=n; }
    }
    __syncthreads();
    for(int n=tid;n<NN;n+=256){
        unsigned int k = __float_as_uint(sed[n]);
        if(k == T){ unsigned int p = atomicAdd(&s_cnt,1u); if(p<KK) sidx[p]=n; }
    }
    __syncthreads();

    // gather dist + edist for the selected set
    for(int k2=tid;k2<KK;k2+=256){
        int n = sidx[k2];
        float d0 = qx - pos[n*2];   d0 += 0.5f; d0 -= floorf(d0); d0 -= 0.5f;
        float d1 = qy - pos[n*2+1]; d1 += 0.5f; d1 -= floorf(d1); d1 -= 0.5f;
        sd0[k2]=d0; sd1[k2]=d1; sedk[k2]=sed[n];
    }
    __syncthreads();

    // min/max over selected
    float mn = 1e30f, mx = -1e30f;
    for(int k2=tid;k2<KK;k2+=256){ mn=fminf(mn,sedk[k2]); mx=fmaxf(mx,sedk[k2]); }
    #pragma unroll
    for(int o=16;o>0;o>>=1){
        mn = fminf(mn, __shfl_down_sync(0xffffffffu,mn,o));
        mx = fmaxf(mx, __shfl_down_sync(0xffffffffu,mx,o));
    }
    if(lane==0){ rbufA[warp]=mn; rbufB[warp]=mx; }
    __syncthreads();
    if(tid==0){
        float a=rbufA[0], b=rbufB[0];
        for(int w=1;w<8;w++){ a=fminf(a,rbufA[w]); b=fmaxf(b,rbufB[w]); }
        s_min=a; s_max=b;
    }
    __syncthreads();

    // softmax weights over K (logit max is exactly 0 at the min-dist element)
    const float inv = 1.0f/(s_max - s_min + 1e-8f);
    float lsum = 0.0f;
    for(int k2=tid;k2<KK;k2+=256){
        float w = expf(-(sedk[k2]-s_min)*inv);
        skd[k2]=w; lsum+=w;
    }
    #pragma unroll
    for(int o=16;o>0;o>>=1) lsum += __shfl_down_sync(0xffffffffu,lsum,o);
    if(lane==0) rbufA[warp]=lsum;
    __syncthreads();
    if(tid==0){
        float s=0.f; for(int w=0;w<8;w++) s+=rbufA[w];
        s_sum=s;
    }
    __syncthreads();
    const float invsum = 1.0f/s_sum;

    // RFF features: feat = [sin(2pi dist@B), cos(2pi dist@B)]
    for(int i=tid;i<KK*16;i+=256){
        int k2=i>>4, j=i&15;
        float pr = 6.28318530717958647692f*(sd0[k2]*rffB[j] + sd1[k2]*rffB[16+j]);
        float s,c; sincosf(pr,&s,&c);
        sfeat[k2][j]=s; sfeat[k2][16+j]=c;
    }
    __syncthreads();

    // h = (feat@W1+b1)*qmw+qmo ; g = gelu(h)*kd, plus kd channel, zero pad
    for(int i=tid;i<KK*CC;i+=256){
        int k2=i>>5, ii=i&31;
        float acc = sb1[ii];
        #pragma unroll
        for(int f=0;f<CC;f++) acc = fmaf(sfeat[k2][f], sW1[f*CC+ii], acc);
        float h  = acc*qmw[q*CC+ii] + qmo[q*CC+ii];
        d_g[(q*KK + k2)*JP + ii] = gelu_f(h) * (skd[k2]*invsum);
    }
    for(int k2=tid;k2<KK;k2+=256){
        float* gr = &d_g[(q*KK + k2)*JP];
        gr[32] = skd[k2]*invsum;
        gr[33] = 0.f; gr[34] = 0.f; gr[35] = 0.f;
        d_ind[q*KK + k2] = sidx[k2];
    }
}

// ---------------- kernel C: gather + M-GEMM + W2 contraction + MLP --------
// dynamic smem layout (floats). Total 24484 floats = 97,936 B -> 2 blocks/SM.
#define KCH 64                    // k-chunk for x staging
#define OFF_G   0                 // 205*36  = 7380   (reused as sh1 2048 later)
#define OFF_X   7380              // 64*256  = 16384  (reused as sM 33*256 = 8448)
#define OFF_IND 23764             // 205 ints (padded to 208)
#define OFF_Y   23972             // 512
#define SMEM_FLOATS 24484
#define SMEM_BYTES (SMEM_FLOATS*4)

__global__ __launch_bounds__(288,2) void k_main(
        const float* __restrict__ W2,  const float* __restrict__ filt,
        const float* __restrict__ bias,
        const float* __restrict__ Wm1, const float* __restrict__ bm1,
        const float* __restrict__ Wm2, const float* __restrict__ bm2,
        float* __restrict__ out)
{
    extern __shared__ float smem[];
    float* sg  = smem + OFF_G;
    float* sx  = smem + OFF_X;
    int*   sind= (int*)(smem + OFF_IND);
    float* sy  = smem + OFF_Y;

    const int q = blockIdx.x, tid = threadIdx.x;
    const int jg = tid>>5;     // 0..8  (j-group of 4)
    const int cg = tid&31;     // 0..31 (col-group of 8, col = b*32+c)

    for(int i=tid;i<KK;i+=288) sind[i]=d_ind[q*KK+i];
    {   const float4* gsrc = (const float4*)&d_g[q*KK*JP];
        float4* gdst = (float4*)sg;
        for(int i=tid;i<KK*(JP/4);i+=288) gdst[i]=gsrc[i];
    }
    __syncthreads();

    float acc[4][8];
    #pragma unroll
    for(int jj=0;jj<4;jj++)
        #pragma unroll
        for(int cc=0;cc<8;cc++) acc[jj][cc]=0.f;

    const float4* sg4 = (const float4*)sg;

    for(int k0=0; k0<KK; k0+=KCH){
        const int nk = (KK - k0 < KCH) ? (KK - k0) : KCH;
        // gather xl rows for all 8 batches: sx[kk][b*32+c]
        for(int i=tid; i<nk*64; i+=288){
            int kk = i>>6, ch = i&63;           // ch = b*8 + c4
            int b  = ch>>3, c4 = ch&7;
            int n  = sind[k0+kk];
            const float4* src = (const float4*)&d_xl[((b<<11)+n)*CC];
            ((float4*)&sx[kk*256])[ch] = src[c4];
        }
        __syncthreads();
        const float4* sx4 = (const float4*)sx;
        #pragma unroll 2
        for(int kk=0; kk<nk; ++kk){
            float4 g4 = sg4[(k0+kk)*(JP/4) + jg];
            float4 xa = sx4[kk*64 + (cg<<1)];
            float4 xb = sx4[kk*64 + (cg<<1) + 1];
            float xs[8] = {xa.x,xa.y,xa.z,xa.w,xb.x,xb.y,xb.z,xb.w};
            float gs[4] = {g4.x,g4.y,g4.z,g4.w};
            #pragma unroll
            for(int jj=0;jj<4;jj++)
                #pragma unroll
                for(int cc=0;cc<8;cc++)
                    acc[jj][cc] = fmaf(gs[jj], xs[cc], acc[jj][cc]);
        }
        __syncthreads();
    }

    // stage M (33 x 256) into smem (aliases sx; all reads done)
    float* sM = sx;
    #pragma unroll
    for(int jj=0;jj<4;jj++){
        int j = jg*4 + jj;
        if(j < 33){
            float4 v0 = make_float4(acc[jj][0],acc[jj][1],acc[jj][2],acc[jj][3]);
            float4 v1 = make_float4(acc[jj][4],acc[jj][5],acc[jj][6],acc[jj][7]);
            ((float4*)&sM[j*256 + cg*8])[0] = v0;
            ((float4*)&sM[j*256 + cg*8])[1] = v1;
        }
    }
    __syncthreads();

    // y[b,d] = sum_{j,c} M[j,b*32+c]*W2ext[j,c,d]
    // 2 batches per thread share each W2 load; 4 independent chains per output.
    for(int o=tid; o<256; o+=288){
        int b = o>>6, d = o&63;                 // b in 0..3, paired with b+4
        float a00=0.f,a01=0.f,a02=0.f,a03=0.f;
        float a10=0.f,a11=0.f,a12=0.f,a13=0.f;
        for(int j=0;j<33;j++){
            const float* wrow = (j<32) ? (W2 + j*2048 + d) : (filt + d);
            const float* m0 = &sM[j*256 + b*32];
            const float* m1 = m0 + 128;
            #pragma unroll
            for(int c=0;c<32;c+=4){
                float w0 = wrow[(c+0)*64];
                float w1 = wrow[(c+1)*64];
                float w2 = wrow[(c+2)*64];
                float w3 = wrow[(c+3)*64];
                a00 = fmaf(m0[c+0], w0, a00);
                a01 = fmaf(m0[c+1], w1, a01);
                a02 = fmaf(m0[c+2], w2, a02);
                a03 = fmaf(m0[c+3], w3, a03);
                a10 = fmaf(m1[c+0], w0, a10);
                a11 = fmaf(m1[c+1], w1, a11);
                a12 = fmaf(m1[c+2], w2, a12);
                a13 = fmaf(m1[c+3], w3, a13);
            }
        }
        float a0 = (a00+a01)+(a02+a03);
        float a1 = (a10+a11)+(a12+a13);
        sy[b*64+d]     = gelu_f(a0 + bias[d]);
        sy[(b+4)*64+d] = gelu_f(a1 + bias[d]);
    }
    __syncthreads();

    // h1 = gelu(y @ Wm1 + bm1)   (sh1 aliases sg; sg no longer needed)
    float* sh1 = sg;
    for(int oi=tid; oi<BB*256; oi+=288){
        int b = oi>>8, i = oi&255;
        float a = bm1[i];
        const float* yr = &sy[b*64];
        #pragma unroll
        for(int d2=0; d2<64; ++d2) a = fmaf(yr[d2], Wm1[d2*256+i], a);
        sh1[oi] = gelu_f(a);
    }
    __syncthreads();

    // out = h1 @ Wm2 + bm2 + y
    for(int o=tid; o<BB*DD; o+=288){
        int b = o>>6, d = o&63;
        float a0=0.f,a1=0.f,a2=0.f,a3=0.f;
        const float* hr = &sh1[b*256];
        #pragma unroll
        for(int i=0;i<256;i+=4){
            a0 = fmaf(hr[i+0], Wm2[(i+0)*64+d], a0);
            a1 = fmaf(hr[i+1], Wm2[(i+1)*64+d], a1);
            a2 = fmaf(hr[i+2], Wm2[(i+2)*64+d], a2);
            a3 = fmaf(hr[i+3], Wm2[(i+3)*64+d], a3);
        }
        out[(b*QQ + q)*DD + d] = (a0+a1)+(a2+a3) + bm2[d] + sy[o];
    }
}

// ---------------- launch --------------------------------------------------
extern "C" void kernel_launch(void* const* d_in, const int* in_sizes, int n_in,
                              void* d_out, int out_size){
    (void)in_sizes; (void)n_in; (void)out_size;
    const float* x     = (const float*)d_in[0];
    const float* pos   = (const float*)d_in[1];
    const float* qpos  = (const float*)d_in[2];
    const float* qmw   = (const float*)d_in[3];
    const float* qmo   = (const float*)d_in[4];
    const float* W_lin = (const float*)d_in[5];
    const float* b_lin = (const float*)d_in[6];
    const float* rffB  = (const float*)d_in[7];
    const float* W1    = (const float*)d_in[8];
    const float* b1    = (const float*)d_in[9];
    const float* W2    = (const float*)d_in[10];
    const float* filt  = (const float*)d_in[11];
    const float* bias  = (const float*)d_in[12];
    const float* Wm1   = (const float*)d_in[13];
    const float* bm1   = (const float*)d_in[14];
    const float* Wm2   = (const float*)d_in[15];
    const float* bm2   = (const float*)d_in[16];
    float* out = (float*)d_out;

    cudaFuncSetAttribute(k_main, cudaFuncAttributeMaxDynamicSharedMemorySize, SMEM_BYTES);

    k_xl    <<<BB*NN/8, 256>>>(x, W_lin, b_lin);
    k_qp    <<<1, 512>>>(qpos, out);
    k_select<<<QQ, 256>>>(pos, qpos, rffB, W1, b1, qmw, qmo);
    k_main  <<<QQ, 288, SMEM_BYTES>>>(W2, filt, bias, Wm1, bm1, Wm2, bm2, out);
}

// round 3
// speedup vs baseline: 1.3481x; 1.1400x over previous
#include <cuda_runtime.h>
#include <math.h>

#define BB 8
#define NN 2048
#define CC 32
#define DD 64
#define QQ 256
#define KK 205
#define JP 36           // padded j dimension (33 -> 36 for float4)
#define RANK (KK-1)
#define NT 288

// ---------------- scratch ----------------
__device__ float d_xl[BB*NN*CC];        // 2 MB

__device__ __forceinline__ float gelu_f(float x){
    return 0.5f*x*(1.0f+erff(x*0.70710678118654752440f));
}

__device__ __forceinline__ void cp_async16(float* smem_dst, const float4* gsrc){
    unsigned sm = (unsigned)__cvta_generic_to_shared(smem_dst);
    asm volatile("cp.async.cg.shared.global [%0], [%1], 16;\n" :: "r"(sm), "l"(gsrc));
}

// ---------------- kernel A: xl = x @ W_lin + b_lin (+ query_pos copy) -----
__global__ __launch_bounds__(256) void k_xl(const float* __restrict__ x,
                                            const float* __restrict__ W,
                                            const float* __restrict__ bl,
                                            const float* __restrict__ qp,
                                            float* __restrict__ out){
    __shared__ float sW[CC*CC];
    int tid = threadIdx.x;
    for(int i=tid;i<CC*CC;i+=256) sW[i]=W[i];
    __syncthreads();
    int row  = blockIdx.x*8 + (tid>>5);
    int lane = tid&31;
    float xv  = x[row*CC + lane];
    float acc = bl[lane];
    #pragma unroll
    for(int ci=0;ci<CC;ci++)
        acc = fmaf(__shfl_sync(0xffffffffu, xv, ci), sW[ci*CC+lane], acc);
    d_xl[row*CC+lane] = acc;
    if(blockIdx.x < 2){
        int i = blockIdx.x*256 + tid;
        out[BB*QQ*DD + i] = qp[i];
    }
}

// ---------------- fused kernel: select + gather + M-GEMM + epilogue + MLP --
// dynamic smem layout (floats). Total 24484 floats = 97,936 B -> 2 blocks/SM.
#define OFF_G   0                 // g: 205*36 = 7380 (later reused as sh1 2048)
#define OFF_X   7380              // 16384: select scratch | 2x gather buffers | sM
#define OFF_IND 23764             // 208 ints
#define OFF_Y   23972             // 512
#define SMEM_FLOATS 24484
#define SMEM_BYTES (SMEM_FLOATS*4)

// select-scratch offsets inside X region:
#define XS_ED    0                // 2048
#define XS_FEAT  2048             // 205*32 = 6560
#define XS_D0    8608             // 205
#define XS_D1    8813             // 205
#define XS_EDK   9018             // 205
#define XS_KD    9223             // 205
#define XS_W1    9428             // 1024
#define XS_B1    10452            // 32
#define XS_HIST  10484            // 256 (uint)
#define XS_RA    10740            // 9
#define XS_RB    10749            // 9
#define XS_SC    10758            // 6 scalars

__global__ __launch_bounds__(NT,2) void k_fused(
        const float* __restrict__ pos, const float* __restrict__ qpos,
        const float* __restrict__ rffB,
        const float* __restrict__ W1,  const float* __restrict__ b1,
        const float* __restrict__ qmw, const float* __restrict__ qmo,
        const float* __restrict__ W2,  const float* __restrict__ filt,
        const float* __restrict__ bias,
        const float* __restrict__ Wm1, const float* __restrict__ bm1,
        const float* __restrict__ Wm2, const float* __restrict__ bm2,
        float* __restrict__ out)
{
    extern __shared__ float smem[];
    float* sg  = smem + OFF_G;
    float* px  = smem + OFF_X;
    int*   sind= (int*)(smem + OFF_IND);
    float* sy  = smem + OFF_Y;

    const int q = blockIdx.x, tid = threadIdx.x;
    const int warp = tid>>5, lane = tid&31;
    const float qx = qpos[q*2], qy = qpos[q*2+1];

    // ======================= SELECT PHASE =======================
    {
        float* sed  = px + XS_ED;
        float* sfeat= px + XS_FEAT;
        float* sd0  = px + XS_D0;
        float* sd1  = px + XS_D1;
        float* sedk = px + XS_EDK;
        float* skd  = px + XS_KD;
        float* sW1  = px + XS_W1;
        float* sb1  = px + XS_B1;
        unsigned int* hist = (unsigned int*)(px + XS_HIST);
        float* rbufA= px + XS_RA;
        float* rbufB= px + XS_RB;
        unsigned int* s_prefix = (unsigned int*)(px + XS_SC);
        unsigned int* s_r      = (unsigned int*)(px + XS_SC + 1);
        unsigned int* s_cnt    = (unsigned int*)(px + XS_SC + 2);
        float* s_min = px + XS_SC + 3;
        float* s_max = px + XS_SC + 4;
        float* s_sum = px + XS_SC + 5;

        for(int i=tid;i<CC*CC;i+=NT) sW1[i]=W1[i];
        if(tid<CC) sb1[tid]=b1[tid];

        // edist (wrapped torus distance)
        for(int n=tid;n<NN;n+=NT){
            float2 p = ((const float2*)pos)[n];
            float d0 = qx - p.x; d0 += 0.5f; d0 -= floorf(d0); d0 -= 0.5f;
            float d1 = qy - p.y; d1 += 0.5f; d1 -= floorf(d1); d1 -= 0.5f;
            sed[n] = d0*d0 + d1*d1;
        }
        if(tid==0){ *s_prefix=0u; *s_r=RANK; *s_cnt=0u; }
        __syncthreads();

        // 4-pass MSD radix select (keys = float bits, all >= 0)
        for(int pass=0; pass<4; ++pass){
            const int shift = 24 - 8*pass;
            for(int i=tid;i<256;i+=NT) hist[i]=0u;
            __syncthreads();
            const unsigned int prefix = *s_prefix;
            const unsigned int hm = (pass==0) ? 0u : (0xFFFFFFFFu << (shift+8));
            for(int n=tid;n<NN;n+=NT){
                unsigned int k = __float_as_uint(sed[n]);
                if((k & hm) == prefix) atomicAdd(&hist[(k>>shift)&255u], 1u);
            }
            __syncthreads();
            if(tid==0){
                unsigned int cum=0, rr=*s_r; int bsel=255;
                for(int bkt=0;bkt<256;bkt++){
                    unsigned int c=hist[bkt];
                    if(cum + c > rr){ bsel=bkt; break; }
                    cum += c;
                }
                *s_prefix = prefix | ((unsigned int)bsel << shift);
                *s_r = rr - cum;
            }
            __syncthreads();
        }
        const unsigned int T = *s_prefix;

        // compact the K nearest: strictly-less first, then equals (capped)
        for(int n=tid;n<NN;n+=NT){
            unsigned int k = __float_as_uint(sed[n]);
            if(k < T){ unsigned int p = atomicAdd(s_cnt,1u); sind[p]=n; }
        }
        __syncthreads();
        for(int n=tid;n<NN;n+=NT){
            unsigned int k = __float_as_uint(sed[n]);
            if(k == T){ unsigned int p = atomicAdd(s_cnt,1u); if(p<KK) sind[p]=n; }
        }
        __syncthreads();

        // gather dist + edist for selected set
        for(int k2=tid;k2<KK;k2+=NT){
            int n = sind[k2];
            float2 p = ((const float2*)pos)[n];
            float d0 = qx - p.x; d0 += 0.5f; d0 -= floorf(d0); d0 -= 0.5f;
            float d1 = qy - p.y; d1 += 0.5f; d1 -= floorf(d1); d1 -= 0.5f;
            sd0[k2]=d0; sd1[k2]=d1; sedk[k2]=sed[n];
        }
        __syncthreads();

        // min/max over selected
        float mn = 1e30f, mx = -1e30f;
        for(int k2=tid;k2<KK;k2+=NT){ mn=fminf(mn,sedk[k2]); mx=fmaxf(mx,sedk[k2]); }
        #pragma unroll
        for(int o=16;o>0;o>>=1){
            mn = fminf(mn, __shfl_down_sync(0xffffffffu,mn,o));
            mx = fmaxf(mx, __shfl_down_sync(0xffffffffu,mx,o));
        }
        if(lane==0){ rbufA[warp]=mn; rbufB[warp]=mx; }
        __syncthreads();
        if(tid==0){
            float a=rbufA[0], b=rbufB[0];
            for(int w=1;w<9;w++){ a=fminf(a,rbufA[w]); b=fmaxf(b,rbufB[w]); }
            *s_min=a; *s_max=b;
        }
        __syncthreads();

        const float inv = 1.0f/(*s_max - *s_min + 1e-8f);
        const float smin = *s_min;
        float lsum = 0.0f;
        for(int k2=tid;k2<KK;k2+=NT){
            float w = expf(-(sedk[k2]-smin)*inv);
            skd[k2]=w; lsum+=w;
        }
        #pragma unroll
        for(int o=16;o>0;o>>=1) lsum += __shfl_down_sync(0xffffffffu,lsum,o);
        if(lane==0) rbufA[warp]=lsum;
        __syncthreads();
        if(tid==0){
            float s=0.f; for(int w=0;w<9;w++) s+=rbufA[w];
            *s_sum=s;
        }
        __syncthreads();
        const float invsum = 1.0f/(*s_sum);

        // RFF features
        for(int i=tid;i<KK*16;i+=NT){
            int k2=i>>4, j=i&15;
            float pr = 6.28318530717958647692f*(sd0[k2]*rffB[j] + sd1[k2]*rffB[16+j]);
            float s,c; sincosf(pr,&s,&c);
            sfeat[k2*32+j]=s; sfeat[k2*32+16+j]=c;
        }
        __syncthreads();

        // g = gelu((feat@W1+b1)*qmw+qmo) * kd ; channel 32 = kd; pad 33..35
        for(int i=tid;i<KK*CC;i+=NT){
            int k2=i>>5, ii=i&31;
            float acc = sb1[ii];
            const float* fr = &sfeat[k2*32];
            #pragma unroll
            for(int f=0;f<CC;f++) acc = fmaf(fr[f], sW1[f*CC+ii], acc);
            float h = acc*qmw[q*CC+ii] + qmo[q*CC+ii];
            sg[k2*JP + ii] = gelu_f(h) * (skd[k2]*invsum);
        }
        for(int k2=tid;k2<KK;k2+=NT){
            sg[k2*JP+32] = skd[k2]*invsum;
            sg[k2*JP+33] = 0.f; sg[k2*JP+34] = 0.f; sg[k2*JP+35] = 0.f;
        }
        __syncthreads();
    }
    // ======================= MAIN PHASE =======================
    const int jg = tid>>5;     // 0..8  (j-group of 4)
    const int cg = tid&31;     // 0..31 (c-quad index)

    float acc[4][8];
    #pragma unroll
    for(int jj=0;jj<4;jj++)
        #pragma unroll
        for(int cc=0;cc<8;cc++) acc[jj][cc]=0.f;

    const float4* sg4 = (const float4*)sg;
    float* xb0 = px;
    float* xb1 = px + 8192;

    // prologue: async-load chunk 0
    {
        for(int i=tid;i<32*64;i+=NT){
            int kk=i>>6, ch=i&63, b=ch>>3, c4=ch&7;
            int n = sind[kk];
            cp_async16(&xb0[kk*256 + ch*4], (const float4*)&d_xl[((b<<11)+n)*CC] + c4);
        }
        asm volatile("cp.async.commit_group;\n");
    }

    const int NCH = (KK + 31)/32;  // 7
    for(int ci=0; ci<NCH; ++ci){
        const int k0 = ci*32;
        const int nk = (KK-k0 < 32) ? (KK-k0) : 32;
        if(ci+1 < NCH){
            const int k0n = k0+32;
            const int nkn = (KK-k0n < 32) ? (KK-k0n) : 32;
            float* dst = (ci&1) ? xb0 : xb1;
            for(int i=tid;i<nkn*64;i+=NT){
                int kk=i>>6, ch=i&63, b=ch>>3, c4=ch&7;
                int n = sind[k0n+kk];
                cp_async16(&dst[kk*256 + ch*4], (const float4*)&d_xl[((b<<11)+n)*CC] + c4);
            }
            asm volatile("cp.async.commit_group;\n");
            asm volatile("cp.async.wait_group 1;\n");
        } else {
            asm volatile("cp.async.wait_group 0;\n");
        }
        __syncthreads();
        const float4* sx4 = (const float4*)((ci&1) ? xb1 : xb0);
        #pragma unroll 2
        for(int kk=0; kk<nk; ++kk){
            float4 g4v = sg4[(k0+kk)*(JP/4) + jg];
            float4 xa = sx4[kk*64 + cg];        // cols [4cg, 4cg+4)    (b 0..3)
            float4 xc = sx4[kk*64 + 32 + cg];   // cols [128+4cg, ...)  (b 4..7)
            float gs[4] = {g4v.x,g4v.y,g4v.z,g4v.w};
            #pragma unroll
            for(int jj=0;jj<4;jj++){
                acc[jj][0] = fmaf(gs[jj], xa.x, acc[jj][0]);
                acc[jj][1] = fmaf(gs[jj], xa.y, acc[jj][1]);
                acc[jj][2] = fmaf(gs[jj], xa.z, acc[jj][2]);
                acc[jj][3] = fmaf(gs[jj], xa.w, acc[jj][3]);
                acc[jj][4] = fmaf(gs[jj], xc.x, acc[jj][4]);
                acc[jj][5] = fmaf(gs[jj], xc.y, acc[jj][5]);
                acc[jj][6] = fmaf(gs[jj], xc.z, acc[jj][6]);
                acc[jj][7] = fmaf(gs[jj], xc.w, acc[jj][7]);
            }
        }
        __syncthreads();
    }

    // stage M (33 x 256) into smem (aliases gather buffers; all reads done)
    float* sM = px;
    #pragma unroll
    for(int jj=0;jj<4;jj++){
        int j = jg*4 + jj;
        if(j < 33){
            *(float4*)&sM[j*256 + 4*cg]       = make_float4(acc[jj][0],acc[jj][1],acc[jj][2],acc[jj][3]);
            *(float4*)&sM[j*256 + 128 + 4*cg] = make_float4(acc[jj][4],acc[jj][5],acc[jj][6],acc[jj][7]);
        }
    }
    __syncthreads();

    // y[b,d] = sum_{j,c} M[j,b*32+c]*W2ext[j,c,d]; 2 batches/thread, 8 chains
    for(int o=tid; o<256; o+=NT){
        int b = o>>6, d = o&63;                 // b in 0..3, paired with b+4
        float a00=0.f,a01=0.f,a02=0.f,a03=0.f;
        float a10=0.f,a11=0.f,a12=0.f,a13=0.f;
        for(int j=0;j<33;j++){
            const float* wrow = (j<32) ? (W2 + j*2048 + d) : (filt + d);
            const float4* m0 = (const float4*)&sM[j*256 + b*32];
            const float4* m1 = (const float4*)&sM[j*256 + 128 + b*32];
            #pragma unroll
            for(int c4=0;c4<8;c4++){
                float4 mv0 = m0[c4];
                float4 mv1 = m1[c4];
                float w0 = wrow[(4*c4+0)*64];
                float w1 = wrow[(4*c4+1)*64];
                float w2 = wrow[(4*c4+2)*64];
                float w3 = wrow[(4*c4+3)*64];
                a00 = fmaf(mv0.x, w0, a00);
                a01 = fmaf(mv0.y, w1, a01);
                a02 = fmaf(mv0.z, w2, a02);
                a03 = fmaf(mv0.w, w3, a03);
                a10 = fmaf(mv1.x, w0, a10);
                a11 = fmaf(mv1.y, w1, a11);
                a12 = fmaf(mv1.z, w2, a12);
                a13 = fmaf(mv1.w, w3, a13);
            }
        }
        float a0 = (a00+a01)+(a02+a03);
        float a1 = (a10+a11)+(a12+a13);
        sy[b*64+d]     = gelu_f(a0 + bias[d]);
        sy[(b+4)*64+d] = gelu_f(a1 + bias[d]);
    }
    __syncthreads();

    // h1 = gelu(y @ Wm1 + bm1)   (sh1 aliases sg)
    float* sh1 = sg;
    for(int oi=tid; oi<BB*256; oi+=NT){
        int b = oi>>8, i = oi&255;
        float a = bm1[i];
        const float* yr = &sy[b*64];
        #pragma unroll
        for(int d2=0; d2<64; ++d2) a = fmaf(yr[d2], Wm1[d2*256+i], a);
        sh1[oi] = gelu_f(a);
    }
    __syncthreads();

    // out = h1 @ Wm2 + bm2 + y
    for(int o=tid; o<BB*DD; o+=NT){
        int b = o>>6, d = o&63;
        float a0=0.f,a1=0.f,a2=0.f,a3=0.f;
        const float* hr = &sh1[b*256];
        #pragma unroll
        for(int i=0;i<256;i+=4){
            a0 = fmaf(hr[i+0], Wm2[(i+0)*64+d], a0);
            a1 = fmaf(hr[i+1], Wm2[(i+1)*64+d], a1);
            a2 = fmaf(hr[i+2], Wm2[(i+2)*64+d], a2);
            a3 = fmaf(hr[i+3], Wm2[(i+3)*64+d], a3);
        }
        out[(b*QQ + q)*DD + d] = (a0+a1)+(a2+a3) + bm2[d] + sy[o];
    }
}

// ---------------- launch --------------------------------------------------
extern "C" void kernel_launch(void* const* d_in, const int* in_sizes, int n_in,
                              void* d_out, int out_size){
    (void)in_sizes; (void)n_in; (void)out_size;
    const float* x     = (const float*)d_in[0];
    const float* pos   = (const float*)d_in[1];
    const float* qpos  = (const float*)d_in[2];
    const float* qmw   = (const float*)d_in[3];
    const float* qmo   = (const float*)d_in[4];
    const float* W_lin = (const float*)d_in[5];
    const float* b_lin = (const float*)d_in[6];
    const float* rffB  = (const float*)d_in[7];
    const float* W1    = (const float*)d_in[8];
    const float* b1    = (const float*)d_in[9];
    const float* W2    = (const float*)d_in[10];
    const float* filt  = (const float*)d_in[11];
    const float* bias  = (const float*)d_in[12];
    const float* Wm1   = (const float*)d_in[13];
    const float* bm1   = (const float*)d_in[14];
    const float* Wm2   = (const float*)d_in[15];
    const float* bm2   = (const float*)d_in[16];
    float* out = (float*)d_out;

    cudaFuncSetAttribute(k_fused, cudaFuncAttributeMaxDynamicSharedMemorySize, SMEM_BYTES);

    k_xl   <<<BB*NN/8, 256>>>(x, W_lin, b_lin, qpos, out);
    k_fused<<<QQ, NT, SMEM_BYTES>>>(pos, qpos, rffB, W1, b1, qmw, qmo,
                                    W2, filt, bias, Wm1, bm1, Wm2, bm2, out);
}